// round 3
// baseline (speedup 1.0000x reference)
#include <cuda_runtime.h>
#include <stdint.h>

#define B_   128
#define S_   512
#define T_   24
#define D_   256
#define H_   4
#define HD_  64
#define N_   (B_*S_)            // 65536
#define NT_  (N_*T_)            // 1572864
#define KOSC (-500.0f)

// Precomputed tables (device globals: no allocation allowed)
__device__ __align__(16) float d_k [H_*T_*HD_];
__device__ __align__(16) float d_v [H_*T_*HD_];
__device__ __align__(16) float d_qt[H_*T_*HD_];
__device__ __align__(16) float d_qu[H_*B_*HD_];
__device__ __align__(16) float d_st[H_*T_*T_];
__device__ __align__(16) float d_su[H_*B_*T_];
__device__ __align__(16) float d_W [96*280];    // [kt=h*24+t][c]: c<256 -> unify, c>=256 -> head
__device__ __align__(16) float d_bias[280];
__device__ unsigned d_ku[2];
__device__ unsigned d_kv[2];

// ---------- JAX threefry2x32 (exact) ----------
__device__ __forceinline__ void tf2x32(unsigned k0, unsigned k1,
                                       unsigned x0, unsigned x1,
                                       unsigned &o0, unsigned &o1) {
    unsigned k2 = k0 ^ k1 ^ 0x1BD11BDAu;
    x0 += k0; x1 += k1;
#define RD_(r) { x0 += x1; x1 = (x1 << (r)) | (x1 >> (32 - (r))); x1 ^= x0; }
    RD_(13) RD_(15) RD_(26) RD_(6)   x0 += k1; x1 += k2 + 1u;
    RD_(17) RD_(29) RD_(16) RD_(24)  x0 += k2; x1 += k0 + 2u;
    RD_(13) RD_(15) RD_(26) RD_(6)   x0 += k0; x1 += k1 + 3u;
    RD_(17) RD_(29) RD_(16) RD_(24)  x0 += k1; x1 += k2 + 4u;
    RD_(13) RD_(15) RD_(26) RD_(6)   x0 += k2; x1 += k0 + 5u;
#undef RD_
    o0 = x0; o1 = x1;
}

// XLA ErfInv32 (Giles polynomial) — matches lax.erf_inv on f32
__device__ __forceinline__ float erfinv_xla(float x) {
    float w = -log1pf(-x * x);
    float p;
    if (w < 5.0f) {
        w = w - 2.5f;
        p =              2.81022636e-08f;
        p = fmaf(p, w,   3.43273939e-07f);
        p = fmaf(p, w,  -3.5233877e-06f);
        p = fmaf(p, w,  -4.39150654e-06f);
        p = fmaf(p, w,   0.00021858087f);
        p = fmaf(p, w,  -0.00125372503f);
        p = fmaf(p, w,  -0.00417768164f);
        p = fmaf(p, w,   0.246640727f);
        p = fmaf(p, w,   1.50140941f);
    } else {
        w = sqrtf(w) - 3.0f;
        p =             -0.000200214257f;
        p = fmaf(p, w,   0.000100950558f);
        p = fmaf(p, w,   0.00134934322f);
        p = fmaf(p, w,  -0.00367342844f);
        p = fmaf(p, w,   0.00573950773f);
        p = fmaf(p, w,  -0.0076224613f);
        p = fmaf(p, w,   0.00943887047f);
        p = fmaf(p, w,   1.00167406f);
        p = fmaf(p, w,   2.83297682f);
    }
    return p * x;
}

// JAX normal(subkey)*0.01 from partitionable-threefry raw bits:
// u01 = bitcast((bits>>9)|0x3f800000)-1 ; val = max(LO, u01*2 + LO)
__device__ __forceinline__ float bits_to_noise(unsigned bits) {
    const float LO = -0.99999994039535522461f;   // nextafter(-1,0) in f32
    float u01 = __uint_as_float((bits >> 9) | 0x3f800000u) - 1.0f;
    float val = fmaxf(LO, u01 * 2.0f + LO);
    float n = 1.41421356237f * erfinv_xla(val);  // sqrt(2)*erfinv
    return n * 0.01f;
}

// ---------- Precompute 1: k, v, qt (per h,t) and qu (per h,b), threefry keys ----------
__global__ void kpre1(const float* __restrict__ ts, const float* __restrict__ sts,
                      const int* __restrict__ user, const float* __restrict__ upref,
                      const float* __restrict__ wq_w, const float* __restrict__ wq_b,
                      const float* __restrict__ wk_w, const float* __restrict__ wk_b,
                      const float* __restrict__ wv_w, const float* __restrict__ wv_b) {
    int bid = blockIdx.x, e = threadIdx.x;
    if (bid == 0 && e == 0) {
        // PARTITIONABLE split (JAX >= 0.5 default):
        // subkey i = (o0, o1) of threefry2x32(key, hi=0, lo=i)
        unsigned a0, a1, b0, b1;
        tf2x32(0u, 42u, 0u, 0u, a0, a1);   // ku
        tf2x32(0u, 42u, 0u, 1u, b0, b1);   // kv
        d_ku[0] = a0; d_ku[1] = a1; d_kv[0] = b0; d_kv[1] = b1;
    }
    if (bid < 96) {
        int h = bid / 24, t = bid % 24;
        const float* xs = sts + t * D_;   // keys use smoothed embeddings
        float ak = wk_b[h*HD_+e], av = wv_b[h*HD_+e];
        for (int d = 0; d < D_; d++) {
            float xv = xs[d];
            ak = fmaf(xv, wk_w[(h*D_ + d)*HD_ + e], ak);
            av = fmaf(xv, wv_w[(h*D_ + d)*HD_ + e], av);
        }
        const float* xt = ts + t * D_;    // query time half uses raw embeddings
        float aq = 0.0f;
        for (int d = 0; d < D_; d++)
            aq = fmaf(xt[d], wq_w[(h*2*D_ + D_ + d)*HD_ + e], aq);
        d_k [bid*HD_ + e] = ak;
        d_v [bid*HD_ + e] = av;
        d_qt[bid*HD_ + e] = aq;
    } else {
        int j = bid - 96, h = j / B_, b = j % B_;
        const float* up = upref + (size_t)user[b] * D_;
        float a = wq_b[h*HD_ + e];
        for (int d = 0; d < D_; d++)
            a = fmaf(up[d], wq_w[(h*2*D_ + d)*HD_ + e], a);
        d_qu[(h*B_ + b)*HD_ + e] = a;
    }
}

// ---------- Precompute 2: W (=v@unify / v@head), st, su, biases ----------
__global__ void kpre2(const float* __restrict__ uw, const float* __restrict__ ub,
                      const float* __restrict__ hw, const float* __restrict__ hb) {
    int bid = blockIdx.x, tid = threadIdx.x;
    if (bid < 96) {
        int h = bid / 24, t = bid % 24, kt = bid;
        {   // U columns
            float a = 0.0f;
            for (int e = 0; e < HD_; e++)
                a = fmaf(d_v[kt*HD_ + e], uw[(h*HD_ + e)*D_ + tid], a);
            d_W[kt*280 + tid] = a;
        }
        if (tid < 24) { // head columns
            float a = 0.0f;
            for (int e = 0; e < HD_; e++)
                a = fmaf(d_v[kt*HD_ + e], hw[(h*HD_ + e)*T_ + tid], a);
            d_W[kt*280 + 256 + tid] = a;
        }
        if (tid >= 32 && tid < 56) { // st[h][tau=t][t2]
            int t2 = tid - 32;
            float a = 0.0f;
            for (int e = 0; e < HD_; e++)
                a = fmaf(d_qt[kt*HD_ + e], d_k[(h*T_ + t2)*HD_ + e], a);
            d_st[(h*T_ + t)*T_ + t2] = a * 0.125f;
        }
        if (bid == 0) d_bias[tid] = ub[tid];
        if (bid == 1 && tid < 24) d_bias[256 + tid] = hb[tid];
    } else {
        int j = bid - 96, h = j / B_, b = j % B_;
        if (tid < 24) {
            float a = 0.0f;
            for (int e = 0; e < HD_; e++)
                a = fmaf(d_qu[(h*B_ + b)*HD_ + e], d_k[(h*T_ + tid)*HD_ + e], a);
            d_su[(h*B_ + b)*T_ + tid] = a * 0.125f;
        }
    }
}

// ---------- Main fused kernel: scores+noise+softmax+GEMM ----------
#define TR_     64
#define PSTRIDE 100
#define SMEM_BYTES ((96*280 + TR_*PSTRIDE) * sizeof(float))

__global__ __launch_bounds__(256) void kmain(const int* __restrict__ hour,
                                             const int* __restrict__ mask,
                                             float* __restrict__ out) {
    extern __shared__ float sh[];
    float* shW = sh;                 // 96*280 floats
    float* shP = sh + 96*280;        // TR_*PSTRIDE floats (z then probs, in place)
    int tid = threadIdx.x;
    int tile0 = blockIdx.x * TR_;

    // Stage W copy (L2 -> smem), 16B vectors
    {
        const float4* Wg = (const float4*)d_W;
        float4* Ws = (float4*)shW;
        for (int i = tid; i < 96*280/4; i += 256) Ws[i] = Wg[i];
    }

    unsigned ku0 = d_ku[0], ku1 = d_ku[1];
    unsigned kv0 = d_kv[0], kv1 = d_kv[1];

    // ---- Stage A: z values (exact JAX partitionable-threefry noise) ----
    for (int slot = tid; slot < TR_*24; slot += 256) {
        int r = slot / 24, t = slot - r*24;
        int n = tile0 + r;
        float* prow = shP + r*PSTRIDE + t;
        int m = mask[n*24 + t];
        if (m) {
            // scores = -inf: relu = 0, gate = exp(-inf) = 0 -> z = 0 exactly
            #pragma unroll
            for (int h = 0; h < 4; h++) prow[h*24] = 0.0f;
            continue;
        }
        int b = n >> 9;                 // S = 512
        int tau = hour[n];
        unsigned ibase = (unsigned)(n*24 + t);
        #pragma unroll
        for (int h = 0; h < 4; h++) {
            float I = d_su[(h*B_ + b)*T_ + t] + d_st[(h*T_ + tau)*T_ + t];
            float g = expf((KOSC * I) * I);
            float z = fmaxf(I, 0.0f);
            if (g != 0.0f) {
                // bits[i] = o0 ^ o1 of threefry2x32(subkey, hi=0, lo=flat_idx)
                unsigned idx = ibase + (unsigned)h * (unsigned)NT_;
                unsigned a0, a1, c0, c1;
                tf2x32(ku0, ku1, 0u, idx, a0, a1);
                tf2x32(kv0, kv1, 0u, idx, c0, c1);
                float dn = bits_to_noise(a0 ^ a1) - bits_to_noise(c0 ^ c1);
                z = z + dn * g;
            }
            prow[h*24] = z;
        }
    }
    __syncthreads();

    // ---- Stage B: softmax per (row, head) over 24 slots, in place ----
    {
        int r = tid >> 2, h = tid & 3;
        float* row = shP + r*PSTRIDE + h*24;
        float mx = -3.402823466e+38f;
        float e[24];
        #pragma unroll
        for (int t = 0; t < 24; t++) mx = fmaxf(mx, row[t]);
        float s = 0.0f;
        #pragma unroll
        for (int t = 0; t < 24; t++) { e[t] = expf(row[t] - mx); s += e[t]; }
        float inv = 1.0f / s;
        #pragma unroll
        for (int t = 0; t < 24; t++) row[t] = e[t] * inv;
    }
    __syncthreads();

    // ---- Stage C: GEMM probs[TR_,96] @ W[96,280] + bias ----
    int rg = tid >> 5;          // 8 rowgroups (one warp each) x 8 rows
    int cs = tid & 31;          // 32 col-sets x 4 cols
    int r0 = rg * 8;
    const float4* Wp = (const float4*)shW;     // row stride 70 float4
    float* outlg = out + (size_t)N_ * D_;
    #pragma unroll
    for (int p = 0; p < 3; p++) {
        int c0 = p*128 + cs*4;
        if (c0 < 280) {
            float acc[8][4];
            #pragma unroll
            for (int i = 0; i < 8; i++)
                acc[i][0] = acc[i][1] = acc[i][2] = acc[i][3] = 0.0f;
            int cw = c0 >> 2;
            #pragma unroll 4
            for (int kk = 0; kk < 96; kk++) {
                float4 w = Wp[kk*70 + cw];
                #pragma unroll
                for (int i = 0; i < 8; i++) {
                    float pr = shP[(r0 + i)*PSTRIDE + kk];
                    acc[i][0] = fmaf(pr, w.x, acc[i][0]);
                    acc[i][1] = fmaf(pr, w.y, acc[i][1]);
                    acc[i][2] = fmaf(pr, w.z, acc[i][2]);
                    acc[i][3] = fmaf(pr, w.w, acc[i][3]);
                }
            }
            float4 bi = *(const float4*)(d_bias + c0);
            #pragma unroll
            for (int i = 0; i < 8; i++) {
                int n = tile0 + r0 + i;
                float4 o = make_float4(acc[i][0] + bi.x, acc[i][1] + bi.y,
                                       acc[i][2] + bi.z, acc[i][3] + bi.w);
                if (c0 < 256)
                    *(float4*)(out + (size_t)n*D_ + c0) = o;
                else
                    *(float4*)(outlg + (size_t)n*T_ + (c0 - 256)) = o;
            }
        }
    }
}

extern "C" void kernel_launch(void* const* d_in, const int* in_sizes, int n_in,
                              void* d_out, int out_size) {
    const float* ts    = (const float*)d_in[0];
    const float* sts   = (const float*)d_in[1];
    // d_in[2] = user_embedded (unused by forward)
    const int*   user  = (const int*)d_in[3];
    const int*   hour  = (const int*)d_in[4];
    const int*   mask  = (const int*)d_in[5];
    const float* upref = (const float*)d_in[6];
    const float* wq_w  = (const float*)d_in[7];
    const float* wq_b  = (const float*)d_in[8];
    const float* wk_w  = (const float*)d_in[9];
    const float* wk_b  = (const float*)d_in[10];
    const float* wv_w  = (const float*)d_in[11];
    const float* wv_b  = (const float*)d_in[12];
    const float* uw    = (const float*)d_in[13];
    const float* ub    = (const float*)d_in[14];
    const float* hw    = (const float*)d_in[15];
    const float* hb    = (const float*)d_in[16];
    float* out = (float*)d_out;

    cudaFuncSetAttribute(kmain, cudaFuncAttributeMaxDynamicSharedMemorySize,
                         (int)SMEM_BYTES);

    kpre1<<<608, 64>>>(ts, sts, user, upref, wq_w, wq_b, wk_w, wk_b, wv_w, wv_b);
    kpre2<<<608, 256>>>(uw, ub, hw, hb);
    kmain<<<N_ / TR_, 256, SMEM_BYTES>>>(hour, mask, out);
}

// round 4
// speedup vs baseline: 1.0880x; 1.0880x over previous
#include <cuda_runtime.h>
#include <stdint.h>

#define B_   128
#define S_   512
#define T_   24
#define D_   256
#define H_   4
#define HD_  64
#define N_   (B_*S_)            // 65536
#define NT_  (N_*T_)            // 1572864
#define KOSC (-500.0f)

typedef unsigned long long ull;

// Precomputed tables (device globals: no allocation allowed)
__device__ __align__(16) float d_k [H_*T_*HD_];
__device__ __align__(16) float d_v [H_*T_*HD_];
__device__ __align__(16) float d_qt[H_*T_*HD_];
__device__ __align__(16) float d_qu[H_*B_*HD_];
__device__ __align__(16) float d_st[H_*T_*T_];
__device__ __align__(16) float d_su[H_*B_*T_];
__device__ __align__(16) float d_W [96*280];    // [kt=h*24+t][c]: c<256 unify, c>=256 head
__device__ __align__(16) float d_bias[280];
__device__ unsigned d_ku[2];
__device__ unsigned d_kv[2];

// ---------- packed f32x2 helpers ----------
__device__ __forceinline__ void ffma2(ull &d, ull a, ull b) {
    asm("fma.rn.f32x2 %0, %1, %2, %0;" : "+l"(d) : "l"(a), "l"(b));
}
__device__ __forceinline__ ull addf2(ull a, ull b) {
    ull r; asm("add.rn.f32x2 %0, %1, %2;" : "=l"(r) : "l"(a), "l"(b)); return r;
}

// ---------- JAX threefry2x32 (exact) ----------
__device__ __forceinline__ void tf2x32(unsigned k0, unsigned k1,
                                       unsigned x0, unsigned x1,
                                       unsigned &o0, unsigned &o1) {
    unsigned k2 = k0 ^ k1 ^ 0x1BD11BDAu;
    x0 += k0; x1 += k1;
#define RD_(r) { x0 += x1; x1 = (x1 << (r)) | (x1 >> (32 - (r))); x1 ^= x0; }
    RD_(13) RD_(15) RD_(26) RD_(6)   x0 += k1; x1 += k2 + 1u;
    RD_(17) RD_(29) RD_(16) RD_(24)  x0 += k2; x1 += k0 + 2u;
    RD_(13) RD_(15) RD_(26) RD_(6)   x0 += k0; x1 += k1 + 3u;
    RD_(17) RD_(29) RD_(16) RD_(24)  x0 += k1; x1 += k2 + 4u;
    RD_(13) RD_(15) RD_(26) RD_(6)   x0 += k2; x1 += k0 + 5u;
#undef RD_
    o0 = x0; o1 = x1;
}

// XLA ErfInv32 (Giles polynomial)
__device__ __forceinline__ float erfinv_xla(float x) {
    float w = -log1pf(-x * x);
    float p;
    if (w < 5.0f) {
        w = w - 2.5f;
        p =              2.81022636e-08f;
        p = fmaf(p, w,   3.43273939e-07f);
        p = fmaf(p, w,  -3.5233877e-06f);
        p = fmaf(p, w,  -4.39150654e-06f);
        p = fmaf(p, w,   0.00021858087f);
        p = fmaf(p, w,  -0.00125372503f);
        p = fmaf(p, w,  -0.00417768164f);
        p = fmaf(p, w,   0.246640727f);
        p = fmaf(p, w,   1.50140941f);
    } else {
        w = sqrtf(w) - 3.0f;
        p =             -0.000200214257f;
        p = fmaf(p, w,   0.000100950558f);
        p = fmaf(p, w,   0.00134934322f);
        p = fmaf(p, w,  -0.00367342844f);
        p = fmaf(p, w,   0.00573950773f);
        p = fmaf(p, w,  -0.0076224613f);
        p = fmaf(p, w,   0.00943887047f);
        p = fmaf(p, w,   1.00167406f);
        p = fmaf(p, w,   2.83297682f);
    }
    return p * x;
}

__device__ __forceinline__ float bits_to_noise(unsigned bits) {
    const float LO = -0.99999994039535522461f;
    float u01 = __uint_as_float((bits >> 9) | 0x3f800000u) - 1.0f;
    float val = fmaxf(LO, u01 * 2.0f + LO);
    return 1.41421356237f * erfinv_xla(val) * 0.01f;
}

// ---------- Precompute 1: k, v, qt (96 units) and qu (512 units) ----------
// block = 256 threads = 4 units x 64 lanes; grid = 152
__global__ __launch_bounds__(256) void kpre1(
        const float* __restrict__ ts, const float* __restrict__ sts,
        const int* __restrict__ user, const float* __restrict__ upref,
        const float* __restrict__ wq_w, const float* __restrict__ wq_b,
        const float* __restrict__ wk_w, const float* __restrict__ wk_b,
        const float* __restrict__ wv_w, const float* __restrict__ wv_b) {
    int unit = blockIdx.x * 4 + (threadIdx.x >> 6);
    int e = threadIdx.x & 63;
    if (blockIdx.x == 0 && threadIdx.x == 0) {
        unsigned a0, a1, b0, b1;
        tf2x32(0u, 42u, 0u, 0u, a0, a1);   // subkey 0 -> ku
        tf2x32(0u, 42u, 0u, 1u, b0, b1);   // subkey 1 -> kv
        d_ku[0] = a0; d_ku[1] = a1; d_kv[0] = b0; d_kv[1] = b1;
    }
    if (unit < 96) {
        int h = unit / 24, t = unit % 24;
        const float* xs = sts + t * D_;
        const float* xt = ts + t * D_;
        const float* wk = wk_w + h*D_*HD_ + e;
        const float* wv = wv_w + h*D_*HD_ + e;
        const float* wq = wq_w + (h*2*D_ + D_)*HD_ + e;
        float k0 = 0, k1 = 0, k2 = 0, k3 = 0;
        float v0 = 0, v1 = 0, v2 = 0, v3 = 0;
        float q0 = 0, q1 = 0, q2 = 0, q3 = 0;
        #pragma unroll 4
        for (int d = 0; d < D_; d += 4) {
            float x0 = xs[d], x1 = xs[d+1], x2 = xs[d+2], x3 = xs[d+3];
            k0 = fmaf(x0, wk[(d  )*HD_], k0); k1 = fmaf(x1, wk[(d+1)*HD_], k1);
            k2 = fmaf(x2, wk[(d+2)*HD_], k2); k3 = fmaf(x3, wk[(d+3)*HD_], k3);
            v0 = fmaf(x0, wv[(d  )*HD_], v0); v1 = fmaf(x1, wv[(d+1)*HD_], v1);
            v2 = fmaf(x2, wv[(d+2)*HD_], v2); v3 = fmaf(x3, wv[(d+3)*HD_], v3);
            float y0 = xt[d], y1 = xt[d+1], y2 = xt[d+2], y3 = xt[d+3];
            q0 = fmaf(y0, wq[(d  )*HD_], q0); q1 = fmaf(y1, wq[(d+1)*HD_], q1);
            q2 = fmaf(y2, wq[(d+2)*HD_], q2); q3 = fmaf(y3, wq[(d+3)*HD_], q3);
        }
        d_k [unit*HD_ + e] = ((wk_b[h*HD_+e] + k0) + k1) + (k2 + k3);
        d_v [unit*HD_ + e] = ((wv_b[h*HD_+e] + v0) + v1) + (v2 + v3);
        d_qt[unit*HD_ + e] = ((q0 + q1) + (q2 + q3));
    } else {
        int j = unit - 96, h = j / B_, b = j % B_;
        const float* up = upref + (size_t)user[b] * D_;
        const float* wq = wq_w + h*2*D_*HD_ + e;
        float a0 = 0, a1 = 0, a2 = 0, a3 = 0;
        #pragma unroll 4
        for (int d = 0; d < D_; d += 4) {
            a0 = fmaf(up[d  ], wq[(d  )*HD_], a0);
            a1 = fmaf(up[d+1], wq[(d+1)*HD_], a1);
            a2 = fmaf(up[d+2], wq[(d+2)*HD_], a2);
            a3 = fmaf(up[d+3], wq[(d+3)*HD_], a3);
        }
        d_qu[(h*B_ + b)*HD_ + e] = ((wq_b[h*HD_+e] + a0) + a1) + (a2 + a3);
    }
}

// ---------- Precompute 2: W, st, su, biases.  grid = 144, block = 256 ----------
__global__ __launch_bounds__(256) void kpre2(
        const float* __restrict__ uw, const float* __restrict__ ub,
        const float* __restrict__ hw, const float* __restrict__ hb) {
    int bid = blockIdx.x, tid = threadIdx.x;
    if (bid < 96) {
        int h = bid / 24, t = bid % 24, kt = bid;
        {   // unify columns, c = tid
            float a0 = 0, a1 = 0, a2 = 0, a3 = 0;
            const float* u = uw + h*HD_*D_ + tid;
            #pragma unroll 4
            for (int e = 0; e < HD_; e += 4) {
                a0 = fmaf(d_v[kt*HD_+e  ], u[(e  )*D_], a0);
                a1 = fmaf(d_v[kt*HD_+e+1], u[(e+1)*D_], a1);
                a2 = fmaf(d_v[kt*HD_+e+2], u[(e+2)*D_], a2);
                a3 = fmaf(d_v[kt*HD_+e+3], u[(e+3)*D_], a3);
            }
            d_W[kt*280 + tid] = (a0 + a1) + (a2 + a3);
        }
        if (tid < 24) { // head columns
            float a0 = 0, a1 = 0;
            const float* hwp = hw + h*HD_*T_ + tid;
            #pragma unroll 4
            for (int e = 0; e < HD_; e += 2) {
                a0 = fmaf(d_v[kt*HD_+e  ], hwp[(e  )*T_], a0);
                a1 = fmaf(d_v[kt*HD_+e+1], hwp[(e+1)*T_], a1);
            }
            d_W[kt*280 + 256 + tid] = a0 + a1;
        }
        if (tid >= 32 && tid < 56) { // st[h][tau=t][t2]
            int t2 = tid - 32;
            float a0 = 0, a1 = 0;
            #pragma unroll 4
            for (int e = 0; e < HD_; e += 2) {
                a0 = fmaf(d_qt[kt*HD_+e  ], d_k[(h*T_+t2)*HD_+e  ], a0);
                a1 = fmaf(d_qt[kt*HD_+e+1], d_k[(h*T_+t2)*HD_+e+1], a1);
            }
            d_st[(h*T_ + t)*T_ + t2] = (a0 + a1) * 0.125f;
        }
        if (bid == 0) d_bias[tid] = ub[tid];
        if (bid == 1 && tid < 24) d_bias[256 + tid] = hb[tid];
    } else {
        // su: 48 blocks x 256 threads = 12288 outputs
        int j = (bid - 96) * 256 + tid;      // j < 12288
        int hb = j / 24, t = j % 24;
        int h = hb >> 7;
        float a0 = 0, a1 = 0, a2 = 0, a3 = 0;
        #pragma unroll 4
        for (int e = 0; e < HD_; e += 4) {
            a0 = fmaf(d_qu[hb*HD_+e  ], d_k[(h*T_+t)*HD_+e  ], a0);
            a1 = fmaf(d_qu[hb*HD_+e+1], d_k[(h*T_+t)*HD_+e+1], a1);
            a2 = fmaf(d_qu[hb*HD_+e+2], d_k[(h*T_+t)*HD_+e+2], a2);
            a3 = fmaf(d_qu[hb*HD_+e+3], d_k[(h*T_+t)*HD_+e+3], a3);
        }
        d_su[hb*T_ + t] = ((a0 + a1) + (a2 + a3)) * 0.125f;
    }
}

// ---------- Main fused kernel ----------
#define TR_   128
#define KS_   98                        // ull stride of shPd rows (even, bank-tuned)
#define SHW_F (96*280)                  // floats
#define SMEM_BYTES (SHW_F*4 + TR_*KS_*8)

__global__ __launch_bounds__(512) void kmain(const int* __restrict__ hour,
                                             const int* __restrict__ mask,
                                             float* __restrict__ out) {
    extern __shared__ float sh[];
    float* shW = sh;                         // 96*280 floats
    ull*   shPd = (ull*)(sh + SHW_F);        // [row][kk] duplicated probs
    int tid = threadIdx.x;
    int tile0 = blockIdx.x * TR_;

    // W copy to smem
    {
        const float4* Wg = (const float4*)d_W;
        float4* Ws = (float4*)shW;
        for (int i = tid; i < SHW_F/4; i += 512) Ws[i] = Wg[i];
    }

    unsigned ku0 = d_ku[0], ku1 = d_ku[1];
    unsigned kv0 = d_kv[0], kv1 = d_kv[1];

    // ---- Stage A+B fused: thread = (row r, head h); z and softmax in registers ----
    {
        int r = tid >> 2, h = tid & 3;
        int n = tile0 + r;
        int b = n >> 9;
        int tau = hour[n];
        const int4*   mp  = (const int4*)(mask + n*24);
        const float4* sup = (const float4*)(d_su + (h*B_ + b)*T_);
        const float4* stp = (const float4*)(d_st + (h*T_ + tau)*T_);
        unsigned ibase = (unsigned)(n*24) + (unsigned)h * (unsigned)NT_;

        float zz[24];
        #pragma unroll
        for (int j = 0; j < 6; j++) {
            int4 m4 = __ldg(mp + j);
            float4 s4 = sup[j];
            float4 t4 = stp[j];
            int tb = j*4;
            int   mv[4] = {m4.x, m4.y, m4.z, m4.w};
            float sv[4] = {s4.x, s4.y, s4.z, s4.w};
            float tv[4] = {t4.x, t4.y, t4.z, t4.w};
            #pragma unroll
            for (int q = 0; q < 4; q++) {
                int t = tb + q;
                float z = 0.0f;
                if (!mv[q]) {
                    float I = sv[q] + tv[q];
                    float g = expf((KOSC * I) * I);
                    z = fmaxf(I, 0.0f);
                    if (g != 0.0f) {
                        unsigned idx = ibase + (unsigned)t;
                        unsigned a0, a1, c0, c1;
                        tf2x32(ku0, ku1, 0u, idx, a0, a1);
                        tf2x32(kv0, kv1, 0u, idx, c0, c1);
                        float dn = bits_to_noise(a0 ^ a1) - bits_to_noise(c0 ^ c1);
                        z = z + dn * g;
                    }
                }
                zz[t] = z;
            }
        }
        // softmax over 24 in registers
        float mx = zz[0];
        #pragma unroll
        for (int t = 1; t < 24; t++) mx = fmaxf(mx, zz[t]);
        float s = 0.0f;
        #pragma unroll
        for (int t = 0; t < 24; t++) { zz[t] = expf(zz[t] - mx); s += zz[t]; }
        float inv = 1.0f / s;
        // write duplicated (p,p) pairs: shPd[r*KS_ + h*24 + t]
        float2* dst = (float2*)(shPd + (size_t)r * KS_ + h*24);
        #pragma unroll
        for (int t = 0; t < 24; t++) {
            float p = zz[t] * inv;
            dst[t] = make_float2(p, p);
        }
    }
    __syncthreads();

    // ---- Stage C: GEMM probs[128,96] @ W[96,280] via fma.rn.f32x2 ----
    float* outlg = out + (size_t)N_ * D_;

    // phase 1: 256 unify cols; 1024 units of (8 rows x 4 cols); 2 per thread
    #pragma unroll
    for (int pass = 0; pass < 2; pass++) {
        int u = tid + pass * 512;
        int rg = u >> 6, cs = u & 63;
        int r0 = rg * 8, c0 = cs * 4;
        ull acc[8][2];
        #pragma unroll
        for (int i = 0; i < 8; i++) { acc[i][0] = 0ull; acc[i][1] = 0ull; }
        #pragma unroll 4
        for (int kk = 0; kk < 96; kk += 2) {
            ulonglong2 wA = *(const ulonglong2*)(shW + kk*280 + c0);
            ulonglong2 wB = *(const ulonglong2*)(shW + (kk+1)*280 + c0);
            #pragma unroll
            for (int i = 0; i < 8; i++) {
                ulonglong2 pr = *(const ulonglong2*)(shPd + (size_t)(r0+i)*KS_ + kk);
                ffma2(acc[i][0], pr.x, wA.x);
                ffma2(acc[i][1], pr.x, wA.y);
                ffma2(acc[i][0], pr.y, wB.x);
                ffma2(acc[i][1], pr.y, wB.y);
            }
        }
        ulonglong2 bi = *(const ulonglong2*)(d_bias + c0);
        #pragma unroll
        for (int i = 0; i < 8; i++) {
            int n = tile0 + r0 + i;
            ulonglong2 o;
            o.x = addf2(acc[i][0], bi.x);
            o.y = addf2(acc[i][1], bi.y);
            *(ulonglong2*)(out + (size_t)n*D_ + c0) = o;
        }
    }

    // phase 2: 24 head cols; 384 units of (4 rows x 2 cols)
    if (tid < 384) {
        int cs = tid % 12, rg = tid / 12;
        int r0 = rg * 4, c0 = 256 + cs * 2;
        ull acc[4] = {0ull, 0ull, 0ull, 0ull};
        #pragma unroll 4
        for (int kk = 0; kk < 96; kk += 2) {
            ull w0 = *(const ull*)(shW + kk*280 + c0);
            ull w1 = *(const ull*)(shW + (kk+1)*280 + c0);
            #pragma unroll
            for (int i = 0; i < 4; i++) {
                ulonglong2 pr = *(const ulonglong2*)(shPd + (size_t)(r0+i)*KS_ + kk);
                ffma2(acc[i], pr.x, w0);
                ffma2(acc[i], pr.y, w1);
            }
        }
        ull bi = *(const ull*)(d_bias + c0);
        #pragma unroll
        for (int i = 0; i < 4; i++) {
            int n = tile0 + r0 + i;
            *(ull*)(outlg + (size_t)n*T_ + (c0 - 256)) = addf2(acc[i], bi);
        }
    }
}

extern "C" void kernel_launch(void* const* d_in, const int* in_sizes, int n_in,
                              void* d_out, int out_size) {
    const float* ts    = (const float*)d_in[0];
    const float* sts   = (const float*)d_in[1];
    const int*   user  = (const int*)d_in[3];
    const int*   hour  = (const int*)d_in[4];
    const int*   mask  = (const int*)d_in[5];
    const float* upref = (const float*)d_in[6];
    const float* wq_w  = (const float*)d_in[7];
    const float* wq_b  = (const float*)d_in[8];
    const float* wk_w  = (const float*)d_in[9];
    const float* wk_b  = (const float*)d_in[10];
    const float* wv_w  = (const float*)d_in[11];
    const float* wv_b  = (const float*)d_in[12];
    const float* uw    = (const float*)d_in[13];
    const float* ub    = (const float*)d_in[14];
    const float* hw    = (const float*)d_in[15];
    const float* hb    = (const float*)d_in[16];
    float* out = (float*)d_out;

    cudaFuncSetAttribute(kmain, cudaFuncAttributeMaxDynamicSharedMemorySize,
                         (int)SMEM_BYTES);

    kpre1<<<152, 256>>>(ts, sts, user, upref, wq_w, wq_b, wk_w, wk_b, wv_w, wv_b);
    kpre2<<<144, 256>>>(uw, ub, hw, hb);
    kmain<<<N_ / TR_, 512, SMEM_BYTES>>>(hour, mask, out);
}

// round 5
// speedup vs baseline: 1.3336x; 1.2257x over previous
#include <cuda_runtime.h>
#include <stdint.h>

#define B_   128
#define S_   512
#define T_   24
#define D_   256
#define H_   4
#define HD_  64
#define N_   (B_*S_)            // 65536
#define NT_  (N_*T_)            // 1572864
#define KOSC (-500.0f)

typedef unsigned long long ull;
typedef unsigned short ushortx;

// Precomputed tables (device globals: no allocation allowed)
__device__ __align__(16) float d_k [H_*T_*HD_];
__device__ __align__(16) float d_v [H_*T_*HD_];
__device__ __align__(16) float d_qt[H_*T_*HD_];
__device__ __align__(16) float d_qu[H_*B_*HD_];
__device__ __align__(16) float d_st[H_*T_*T_];
__device__ __align__(16) float d_su[H_*B_*T_];
__device__ __align__(16) float d_W [96*280];
__device__ __align__(16) float d_bias[280];
__device__ unsigned d_ku[2];
__device__ unsigned d_kv[2];

// ---------- packed f32x2 helpers ----------
__device__ __forceinline__ void ffma2(ull &d, ull a, ull b) {
    asm("fma.rn.f32x2 %0, %1, %2, %0;" : "+l"(d) : "l"(a), "l"(b));
}
__device__ __forceinline__ ull addf2(ull a, ull b) {
    ull r; asm("add.rn.f32x2 %0, %1, %2;" : "=l"(r) : "l"(a), "l"(b)); return r;
}

// ---------- JAX threefry2x32 (exact) ----------
__device__ __forceinline__ void tf2x32(unsigned k0, unsigned k1,
                                       unsigned x0, unsigned x1,
                                       unsigned &o0, unsigned &o1) {
    unsigned k2 = k0 ^ k1 ^ 0x1BD11BDAu;
    x0 += k0; x1 += k1;
#define RD_(r) { x0 += x1; x1 = (x1 << (r)) | (x1 >> (32 - (r))); x1 ^= x0; }
    RD_(13) RD_(15) RD_(26) RD_(6)   x0 += k1; x1 += k2 + 1u;
    RD_(17) RD_(29) RD_(16) RD_(24)  x0 += k2; x1 += k0 + 2u;
    RD_(13) RD_(15) RD_(26) RD_(6)   x0 += k0; x1 += k1 + 3u;
    RD_(17) RD_(29) RD_(16) RD_(24)  x0 += k1; x1 += k2 + 4u;
    RD_(13) RD_(15) RD_(26) RD_(6)   x0 += k2; x1 += k0 + 5u;
#undef RD_
    o0 = x0; o1 = x1;
}

// XLA ErfInv32 (Giles polynomial)
__device__ __forceinline__ float erfinv_xla(float x) {
    float w = -log1pf(-x * x);
    float p;
    if (w < 5.0f) {
        w = w - 2.5f;
        p =              2.81022636e-08f;
        p = fmaf(p, w,   3.43273939e-07f);
        p = fmaf(p, w,  -3.5233877e-06f);
        p = fmaf(p, w,  -4.39150654e-06f);
        p = fmaf(p, w,   0.00021858087f);
        p = fmaf(p, w,  -0.00125372503f);
        p = fmaf(p, w,  -0.00417768164f);
        p = fmaf(p, w,   0.246640727f);
        p = fmaf(p, w,   1.50140941f);
    } else {
        w = sqrtf(w) - 3.0f;
        p =             -0.000200214257f;
        p = fmaf(p, w,   0.000100950558f);
        p = fmaf(p, w,   0.00134934322f);
        p = fmaf(p, w,  -0.00367342844f);
        p = fmaf(p, w,   0.00573950773f);
        p = fmaf(p, w,  -0.0076224613f);
        p = fmaf(p, w,   0.00943887047f);
        p = fmaf(p, w,   1.00167406f);
        p = fmaf(p, w,   2.83297682f);
    }
    return p * x;
}

__device__ __forceinline__ float bits_to_noise(unsigned bits) {
    const float LO = -0.99999994039535522461f;
    float u01 = __uint_as_float((bits >> 9) | 0x3f800000u) - 1.0f;
    float val = fmaxf(LO, u01 * 2.0f + LO);
    return 1.41421356237f * erfinv_xla(val) * 0.01f;
}

// ---------- Precompute 1 (split-K over D): 608 blocks x 256 threads ----------
// block = 1 unit; thread = (e in 0..63, part in 0..3); part sums 64 d's.
__global__ __launch_bounds__(256) void kpre1(
        const float* __restrict__ ts, const float* __restrict__ sts,
        const int* __restrict__ user, const float* __restrict__ upref,
        const float* __restrict__ wq_w, const float* __restrict__ wq_b,
        const float* __restrict__ wk_w, const float* __restrict__ wk_b,
        const float* __restrict__ wv_w, const float* __restrict__ wv_b) {
    __shared__ float red[3][4][64];
    int unit = blockIdx.x;
    int e = threadIdx.x & 63, part = threadIdx.x >> 6;
    int d0 = part * 64;
    if (blockIdx.x == 0 && threadIdx.x == 0) {
        unsigned a0, a1, b0, b1;
        tf2x32(0u, 42u, 0u, 0u, a0, a1);
        tf2x32(0u, 42u, 0u, 1u, b0, b1);
        d_ku[0] = a0; d_ku[1] = a1; d_kv[0] = b0; d_kv[1] = b1;
    }
    if (unit < 96) {
        int h = unit / 24, t = unit % 24;
        const float* xs = sts + t * D_ + d0;
        const float* xt = ts  + t * D_ + d0;
        const float* wk = wk_w + (h*D_ + d0)*HD_ + e;
        const float* wv = wv_w + (h*D_ + d0)*HD_ + e;
        const float* wq = wq_w + (h*2*D_ + D_ + d0)*HD_ + e;
        float k0=0,k1=0,k2=0,k3=0, v0=0,v1=0,v2=0,v3=0, q0=0,q1=0,q2=0,q3=0;
        #pragma unroll 4
        for (int d = 0; d < 64; d += 4) {
            float x0 = xs[d], x1 = xs[d+1], x2 = xs[d+2], x3 = xs[d+3];
            k0 = fmaf(x0, wk[(d  )*HD_], k0); k1 = fmaf(x1, wk[(d+1)*HD_], k1);
            k2 = fmaf(x2, wk[(d+2)*HD_], k2); k3 = fmaf(x3, wk[(d+3)*HD_], k3);
            v0 = fmaf(x0, wv[(d  )*HD_], v0); v1 = fmaf(x1, wv[(d+1)*HD_], v1);
            v2 = fmaf(x2, wv[(d+2)*HD_], v2); v3 = fmaf(x3, wv[(d+3)*HD_], v3);
            float y0 = xt[d], y1 = xt[d+1], y2 = xt[d+2], y3 = xt[d+3];
            q0 = fmaf(y0, wq[(d  )*HD_], q0); q1 = fmaf(y1, wq[(d+1)*HD_], q1);
            q2 = fmaf(y2, wq[(d+2)*HD_], q2); q3 = fmaf(y3, wq[(d+3)*HD_], q3);
        }
        red[0][part][e] = (k0 + k1) + (k2 + k3);
        red[1][part][e] = (v0 + v1) + (v2 + v3);
        red[2][part][e] = (q0 + q1) + (q2 + q3);
        __syncthreads();
        if (part < 3) {
            float s = (red[part][0][e] + red[part][1][e])
                    + (red[part][2][e] + red[part][3][e]);
            if      (part == 0) d_k [unit*HD_ + e] = s + wk_b[h*HD_ + e];
            else if (part == 1) d_v [unit*HD_ + e] = s + wv_b[h*HD_ + e];
            else                d_qt[unit*HD_ + e] = s;
        }
    } else {
        int j = unit - 96, h = j / B_, b = j % B_;
        const float* up = upref + (size_t)user[b] * D_ + d0;
        const float* wq = wq_w + (h*2*D_ + d0)*HD_ + e;
        float a0=0, a1=0, a2=0, a3=0;
        #pragma unroll 4
        for (int d = 0; d < 64; d += 4) {
            a0 = fmaf(up[d  ], wq[(d  )*HD_], a0);
            a1 = fmaf(up[d+1], wq[(d+1)*HD_], a1);
            a2 = fmaf(up[d+2], wq[(d+2)*HD_], a2);
            a3 = fmaf(up[d+3], wq[(d+3)*HD_], a3);
        }
        red[0][part][e] = (a0 + a1) + (a2 + a3);
        __syncthreads();
        if (part == 0) {
            float s = (red[0][0][e] + red[0][1][e])
                    + (red[0][2][e] + red[0][3][e]);
            d_qu[(h*B_ + b)*HD_ + e] = s + wq_b[h*HD_ + e];
        }
    }
}

// ---------- Precompute 2: W, st, su, biases.  grid = 144, block = 256 ----------
__global__ __launch_bounds__(256) void kpre2(
        const float* __restrict__ uw, const float* __restrict__ ub,
        const float* __restrict__ hw, const float* __restrict__ hb) {
    int bid = blockIdx.x, tid = threadIdx.x;
    if (bid < 96) {
        int h = bid / 24, t = bid % 24, kt = bid;
        {
            float a0 = 0, a1 = 0, a2 = 0, a3 = 0;
            const float* u = uw + h*HD_*D_ + tid;
            #pragma unroll 4
            for (int e = 0; e < HD_; e += 4) {
                a0 = fmaf(d_v[kt*HD_+e  ], u[(e  )*D_], a0);
                a1 = fmaf(d_v[kt*HD_+e+1], u[(e+1)*D_], a1);
                a2 = fmaf(d_v[kt*HD_+e+2], u[(e+2)*D_], a2);
                a3 = fmaf(d_v[kt*HD_+e+3], u[(e+3)*D_], a3);
            }
            d_W[kt*280 + tid] = (a0 + a1) + (a2 + a3);
        }
        if (tid < 24) {
            float a0 = 0, a1 = 0;
            const float* hwp = hw + h*HD_*T_ + tid;
            #pragma unroll 4
            for (int e = 0; e < HD_; e += 2) {
                a0 = fmaf(d_v[kt*HD_+e  ], hwp[(e  )*T_], a0);
                a1 = fmaf(d_v[kt*HD_+e+1], hwp[(e+1)*T_], a1);
            }
            d_W[kt*280 + 256 + tid] = a0 + a1;
        }
        if (tid >= 32 && tid < 56) {
            int t2 = tid - 32;
            float a0 = 0, a1 = 0;
            #pragma unroll 4
            for (int e = 0; e < HD_; e += 2) {
                a0 = fmaf(d_qt[kt*HD_+e  ], d_k[(h*T_+t2)*HD_+e  ], a0);
                a1 = fmaf(d_qt[kt*HD_+e+1], d_k[(h*T_+t2)*HD_+e+1], a1);
            }
            d_st[(h*T_ + t)*T_ + t2] = (a0 + a1) * 0.125f;
        }
        if (bid == 0) d_bias[tid] = ub[tid];
        if (bid == 1 && tid < 24) d_bias[256 + tid] = hb[tid];
    } else {
        int j = (bid - 96) * 256 + tid;
        int hb2 = j / 24, t = j % 24;
        int h = hb2 >> 7;
        float a0 = 0, a1 = 0, a2 = 0, a3 = 0;
        #pragma unroll 4
        for (int e = 0; e < HD_; e += 4) {
            a0 = fmaf(d_qu[hb2*HD_+e  ], d_k[(h*T_+t)*HD_+e  ], a0);
            a1 = fmaf(d_qu[hb2*HD_+e+1], d_k[(h*T_+t)*HD_+e+1], a1);
            a2 = fmaf(d_qu[hb2*HD_+e+2], d_k[(h*T_+t)*HD_+e+2], a2);
            a3 = fmaf(d_qu[hb2*HD_+e+3], d_k[(h*T_+t)*HD_+e+3], a3);
        }
        d_su[hb2*T_ + t] = ((a0 + a1) + (a2 + a3)) * 0.125f;
    }
}

// ---------- Main fused kernel ----------
#define TR_    128
#define KS_    98                       // ull stride of shPd rows
#define ZS_    97                       // float stride of shZ rows (conflict-free)
#define SHW_F  (96*280)                 // 26880 floats
#define SHPD_B (TR_*KS_*8)              // 100352 bytes
#define REG1_B (SHW_F*4)                // 107520 bytes >= shZ(49664)+queue(24576)
#define SMEM_BYTES (SHPD_B + REG1_B)

__global__ __launch_bounds__(512) void kmain(const int* __restrict__ hour,
                                             const int* __restrict__ mask,
                                             float* __restrict__ out) {
    extern __shared__ char smembuf[];
    ull*   shPd  = (ull*)smembuf;                      // probs, duplicated pairs
    float* shZ   = (float*)(smembuf + SHPD_B);         // z staging [128][97]
    ushortx* queue = (ushortx*)(smembuf + SHPD_B + TR_*ZS_*4);
    float* shW   = (float*)(smembuf + SHPD_B);         // overlays shZ/queue later
    __shared__ int cnt;

    int tid = threadIdx.x;
    int lane = tid & 31;
    int tile0 = blockIdx.x * TR_;
    if (tid == 0) cnt = 0;
    __syncthreads();

    // ---- Stage A1: z = relu(I) for all slots; queue slots needing noise ----
    {
        int r = tid >> 2, h = tid & 3;
        int n = tile0 + r;
        int b = n >> 9;
        int tau = hour[n];
        const int4*   mp  = (const int4*)(mask + n*24);
        const float4* sup = (const float4*)(d_su + (h*B_ + b)*T_);
        const float4* stp = (const float4*)(d_st + (h*T_ + tau)*T_);
        float* zrow = shZ + r*ZS_ + h*24;
        #pragma unroll
        for (int j = 0; j < 6; j++) {
            int4 m4 = __ldg(mp + j);
            float4 s4 = sup[j];
            float4 t4 = stp[j];
            int   mv[4] = {m4.x, m4.y, m4.z, m4.w};
            float sv[4] = {s4.x, s4.y, s4.z, s4.w};
            float tv[4] = {t4.x, t4.y, t4.z, t4.w};
            #pragma unroll
            for (int q = 0; q < 4; q++) {
                int t = j*4 + q;
                float z = 0.0f;
                bool need = false;
                if (!mv[q]) {
                    float I = sv[q] + tv[q];
                    float g = expf((KOSC * I) * I);
                    z = fmaxf(I, 0.0f);
                    need = (g != 0.0f);
                }
                zrow[t] = z;
                unsigned bal = __ballot_sync(0xffffffffu, need);
                if (bal) {
                    int leader = __ffs(bal) - 1;
                    int npush = __popc(bal);
                    int base = 0;
                    if (lane == leader) base = atomicAdd(&cnt, npush);
                    base = __shfl_sync(0xffffffffu, base, leader);
                    if (need) {
                        int rank = __popc(bal & ((1u << lane) - 1u));
                        queue[base + rank] = (ushortx)(tid*24 + t);
                    }
                }
            }
        }
    }
    __syncthreads();

    // ---- Stage A2: dense threefry over queued slots ----
    {
        unsigned ku0 = d_ku[0], ku1 = d_ku[1];
        unsigned kv0 = d_kv[0], kv1 = d_kv[1];
        int total = cnt;
        for (int i = tid; i < total; i += 512) {
            int sid = queue[i];
            int t = sid % 24;
            int rh = sid / 24;
            int r = rh >> 2, h = rh & 3;
            int n = tile0 + r;
            int b = n >> 9;
            int tau = hour[n];
            float I = d_su[(h*B_ + b)*T_ + t] + d_st[(h*T_ + tau)*T_ + t];
            float g = expf((KOSC * I) * I);   // bit-identical recompute
            unsigned idx = (unsigned)(n*24 + t) + (unsigned)h * (unsigned)NT_;
            unsigned a0, a1, c0, c1;
            tf2x32(ku0, ku1, 0u, idx, a0, a1);
            tf2x32(kv0, kv1, 0u, idx, c0, c1);
            float dn = bits_to_noise(a0 ^ a1) - bits_to_noise(c0 ^ c1);
            shZ[r*ZS_ + h*24 + t] += dn * g;
        }
    }
    __syncthreads();

    // ---- Stage B: softmax per (row, head), write duplicated pairs ----
    {
        int r = tid >> 2, h = tid & 3;
        const float* zrow = shZ + r*ZS_ + h*24;
        float zz[24];
        #pragma unroll
        for (int t = 0; t < 24; t++) zz[t] = zrow[t];
        float mx = zz[0];
        #pragma unroll
        for (int t = 1; t < 24; t++) mx = fmaxf(mx, zz[t]);
        float s = 0.0f;
        #pragma unroll
        for (int t = 0; t < 24; t++) { zz[t] = expf(zz[t] - mx); s += zz[t]; }
        float inv = 1.0f / s;
        float2* dst = (float2*)(shPd + (size_t)r * KS_ + h*24);
        #pragma unroll
        for (int t = 0; t < 24; t++) {
            float p = zz[t] * inv;
            dst[t] = make_float2(p, p);
        }
    }
    __syncthreads();

    // ---- Load W into smem (overlays shZ/queue) ----
    {
        const float4* Wg = (const float4*)d_W;
        float4* Ws = (float4*)shW;
        for (int i = tid; i < SHW_F/4; i += 512) Ws[i] = Wg[i];
    }
    __syncthreads();

    // ---- Stage C: GEMM probs[128,96] @ W[96,280] via fma.rn.f32x2 ----
    float* outlg = out + (size_t)N_ * D_;

    #pragma unroll
    for (int pass = 0; pass < 2; pass++) {
        int u = tid + pass * 512;
        int rg = u >> 6, cs = u & 63;
        int r0 = rg * 8, c0 = cs * 4;
        ull acc[8][2];
        #pragma unroll
        for (int i = 0; i < 8; i++) { acc[i][0] = 0ull; acc[i][1] = 0ull; }
        #pragma unroll 4
        for (int kk = 0; kk < 96; kk += 2) {
            ulonglong2 wA = *(const ulonglong2*)(shW + kk*280 + c0);
            ulonglong2 wB = *(const ulonglong2*)(shW + (kk+1)*280 + c0);
            #pragma unroll
            for (int i = 0; i < 8; i++) {
                ulonglong2 pr = *(const ulonglong2*)(shPd + (size_t)(r0+i)*KS_ + kk);
                ffma2(acc[i][0], pr.x, wA.x);
                ffma2(acc[i][1], pr.x, wA.y);
                ffma2(acc[i][0], pr.y, wB.x);
                ffma2(acc[i][1], pr.y, wB.y);
            }
        }
        ulonglong2 bi = *(const ulonglong2*)(d_bias + c0);
        #pragma unroll
        for (int i = 0; i < 8; i++) {
            int n = tile0 + r0 + i;
            ulonglong2 o;
            o.x = addf2(acc[i][0], bi.x);
            o.y = addf2(acc[i][1], bi.y);
            *(ulonglong2*)(out + (size_t)n*D_ + c0) = o;
        }
    }

    if (tid < 384) {
        int cs = tid % 12, rg = tid / 12;
        int r0 = rg * 4, c0 = 256 + cs * 2;
        ull acc[4] = {0ull, 0ull, 0ull, 0ull};
        #pragma unroll 4
        for (int kk = 0; kk < 96; kk += 2) {
            ull w0 = *(const ull*)(shW + kk*280 + c0);
            ull w1 = *(const ull*)(shW + (kk+1)*280 + c0);
            #pragma unroll
            for (int i = 0; i < 4; i++) {
                ulonglong2 pr = *(const ulonglong2*)(shPd + (size_t)(r0+i)*KS_ + kk);
                ffma2(acc[i], pr.x, w0);
                ffma2(acc[i], pr.y, w1);
            }
        }
        ull bi = *(const ull*)(d_bias + c0);
        #pragma unroll
        for (int i = 0; i < 4; i++) {
            int n = tile0 + r0 + i;
            *(ull*)(outlg + (size_t)n*T_ + (c0 - 256)) = addf2(acc[i], bi);
        }
    }
}

extern "C" void kernel_launch(void* const* d_in, const int* in_sizes, int n_in,
                              void* d_out, int out_size) {
    const float* ts    = (const float*)d_in[0];
    const float* sts   = (const float*)d_in[1];
    const int*   user  = (const int*)d_in[3];
    const int*   hour  = (const int*)d_in[4];
    const int*   mask  = (const int*)d_in[5];
    const float* upref = (const float*)d_in[6];
    const float* wq_w  = (const float*)d_in[7];
    const float* wq_b  = (const float*)d_in[8];
    const float* wk_w  = (const float*)d_in[9];
    const float* wk_b  = (const float*)d_in[10];
    const float* wv_w  = (const float*)d_in[11];
    const float* wv_b  = (const float*)d_in[12];
    const float* uw    = (const float*)d_in[13];
    const float* ub    = (const float*)d_in[14];
    const float* hw    = (const float*)d_in[15];
    const float* hb    = (const float*)d_in[16];
    float* out = (float*)d_out;

    cudaFuncSetAttribute(kmain, cudaFuncAttributeMaxDynamicSharedMemorySize,
                         (int)SMEM_BYTES);

    kpre1<<<608, 256>>>(ts, sts, user, upref, wq_w, wq_b, wk_w, wk_b, wv_w, wv_b);
    kpre2<<<144, 256>>>(uw, ub, hw, hb);
    kmain<<<N_ / TR_, 512, SMEM_BYTES>>>(hour, mask, out);
}

// round 8
// speedup vs baseline: 1.4083x; 1.0560x over previous
#include <cuda_runtime.h>
#include <stdint.h>

#define B_   128
#define S_   512
#define T_   24
#define D_   256
#define H_   4
#define HD_  64
#define N_   (B_*S_)            // 65536
#define NT_  (N_*T_)            // 1572864
#define KOSC (-500.0f)

typedef unsigned long long ull;
typedef unsigned short ushortx;

// Precomputed tables (device globals: no allocation allowed)
__device__ __align__(16) float d_k [H_*T_*HD_];
__device__ __align__(16) float d_v [H_*T_*HD_];
__device__ __align__(16) float d_qt[H_*T_*HD_];
__device__ __align__(16) float d_qu[H_*B_*HD_];
__device__ __align__(16) float d_st[H_*T_*T_];
__device__ __align__(16) float d_su[H_*B_*T_];
__device__ __align__(16) float d_W [96*280];   // [kt][c]: c<256 unify, c>=256 head
__device__ __align__(16) float d_bias[280];
__device__ unsigned d_ku[2];
__device__ unsigned d_kv[2];

// ---------- packed f32x2 helpers ----------
__device__ __forceinline__ void ffma2(ull &d, ull a, ull b) {
    asm("fma.rn.f32x2 %0, %1, %2, %0;" : "+l"(d) : "l"(a), "l"(b));
}
__device__ __forceinline__ ull addf2(ull a, ull b) {
    ull r; asm("add.rn.f32x2 %0, %1, %2;" : "=l"(r) : "l"(a), "l"(b)); return r;
}

// ---------- JAX threefry2x32 (exact) ----------
__device__ __forceinline__ void tf2x32(unsigned k0, unsigned k1,
                                       unsigned x0, unsigned x1,
                                       unsigned &o0, unsigned &o1) {
    unsigned k2 = k0 ^ k1 ^ 0x1BD11BDAu;
    x0 += k0; x1 += k1;
#define RD_(r) { x0 += x1; x1 = (x1 << (r)) | (x1 >> (32 - (r))); x1 ^= x0; }
    RD_(13) RD_(15) RD_(26) RD_(6)   x0 += k1; x1 += k2 + 1u;
    RD_(17) RD_(29) RD_(16) RD_(24)  x0 += k2; x1 += k0 + 2u;
    RD_(13) RD_(15) RD_(26) RD_(6)   x0 += k0; x1 += k1 + 3u;
    RD_(17) RD_(29) RD_(16) RD_(24)  x0 += k1; x1 += k2 + 4u;
    RD_(13) RD_(15) RD_(26) RD_(6)   x0 += k2; x1 += k0 + 5u;
#undef RD_
    o0 = x0; o1 = x1;
}

__device__ __forceinline__ float erfinv_xla(float x) {
    float w = -log1pf(-x * x);
    float p;
    if (w < 5.0f) {
        w = w - 2.5f;
        p =              2.81022636e-08f;
        p = fmaf(p, w,   3.43273939e-07f);
        p = fmaf(p, w,  -3.5233877e-06f);
        p = fmaf(p, w,  -4.39150654e-06f);
        p = fmaf(p, w,   0.00021858087f);
        p = fmaf(p, w,  -0.00125372503f);
        p = fmaf(p, w,  -0.00417768164f);
        p = fmaf(p, w,   0.246640727f);
        p = fmaf(p, w,   1.50140941f);
    } else {
        w = sqrtf(w) - 3.0f;
        p =             -0.000200214257f;
        p = fmaf(p, w,   0.000100950558f);
        p = fmaf(p, w,   0.00134934322f);
        p = fmaf(p, w,  -0.00367342844f);
        p = fmaf(p, w,   0.00573950773f);
        p = fmaf(p, w,  -0.0076224613f);
        p = fmaf(p, w,   0.00943887047f);
        p = fmaf(p, w,   1.00167406f);
        p = fmaf(p, w,   2.83297682f);
    }
    return p * x;
}

__device__ __forceinline__ float bits_to_noise(unsigned bits) {
    const float LO = -0.99999994039535522461f;
    float u01 = __uint_as_float((bits >> 9) | 0x3f800000u) - 1.0f;
    float val = fmaxf(LO, u01 * 2.0f + LO);
    return 1.41421356237f * erfinv_xla(val) * 0.01f;
}

// ---------- Precompute 1: 96 ktv blocks + 128 qu blocks (4 users each) ----------
__global__ __launch_bounds__(512) void kpre1(
        const float* __restrict__ ts, const float* __restrict__ sts,
        const int* __restrict__ user, const float* __restrict__ upref,
        const float* __restrict__ wq_w, const float* __restrict__ wq_b,
        const float* __restrict__ wk_w, const float* __restrict__ wk_b,
        const float* __restrict__ wv_w, const float* __restrict__ wv_b) {
    __shared__ float redbuf[2048];
    int unit = blockIdx.x;
    int e = threadIdx.x & 63, part = threadIdx.x >> 6;
    int d0 = part * 32;
    if (blockIdx.x == 0 && threadIdx.x == 0) {
        unsigned a0, a1, b0, b1;
        tf2x32(0u, 42u, 0u, 0u, a0, a1);
        tf2x32(0u, 42u, 0u, 1u, b0, b1);
        d_ku[0] = a0; d_ku[1] = a1; d_kv[0] = b0; d_kv[1] = b1;
    }
    if (unit < 96) {
        float (*red)[8][64] = (float(*)[8][64])redbuf;
        int h = unit / 24, t = unit % 24;
        const float* xs = sts + t * D_ + d0;
        const float* xt = ts  + t * D_ + d0;
        const float* wk = wk_w + (h*D_ + d0)*HD_ + e;
        const float* wv = wv_w + (h*D_ + d0)*HD_ + e;
        const float* wq = wq_w + (h*2*D_ + D_ + d0)*HD_ + e;
        float k0=0,k1=0,k2=0,k3=0, v0=0,v1=0,v2=0,v3=0, q0=0,q1=0,q2=0,q3=0;
        #pragma unroll
        for (int d = 0; d < 32; d += 4) {
            float x0 = xs[d], x1 = xs[d+1], x2 = xs[d+2], x3 = xs[d+3];
            k0 = fmaf(x0, wk[(d  )*HD_], k0); k1 = fmaf(x1, wk[(d+1)*HD_], k1);
            k2 = fmaf(x2, wk[(d+2)*HD_], k2); k3 = fmaf(x3, wk[(d+3)*HD_], k3);
            v0 = fmaf(x0, wv[(d  )*HD_], v0); v1 = fmaf(x1, wv[(d+1)*HD_], v1);
            v2 = fmaf(x2, wv[(d+2)*HD_], v2); v3 = fmaf(x3, wv[(d+3)*HD_], v3);
            float y0 = xt[d], y1 = xt[d+1], y2 = xt[d+2], y3 = xt[d+3];
            q0 = fmaf(y0, wq[(d  )*HD_], q0); q1 = fmaf(y1, wq[(d+1)*HD_], q1);
            q2 = fmaf(y2, wq[(d+2)*HD_], q2); q3 = fmaf(y3, wq[(d+3)*HD_], q3);
        }
        red[0][part][e] = (k0 + k1) + (k2 + k3);
        red[1][part][e] = (v0 + v1) + (v2 + v3);
        red[2][part][e] = (q0 + q1) + (q2 + q3);
        __syncthreads();
        if (part < 3) {
            float s = ((red[part][0][e] + red[part][1][e])
                     + (red[part][2][e] + red[part][3][e]))
                    + ((red[part][4][e] + red[part][5][e])
                     + (red[part][6][e] + red[part][7][e]));
            if      (part == 0) d_k [unit*HD_ + e] = s + wk_b[h*HD_ + e];
            else if (part == 1) d_v [unit*HD_ + e] = s + wv_b[h*HD_ + e];
            else                d_qt[unit*HD_ + e] = s;
        }
    } else {
        float (*red)[64][4] = (float(*)[64][4])redbuf;
        int j = unit - 96;                 // 0..127
        int h = j >> 5;                    // 0..3
        int bg = (j & 31) * 4;             // base user row
        const float* up0 = upref + (size_t)user[bg+0]*D_ + d0;
        const float* up1 = upref + (size_t)user[bg+1]*D_ + d0;
        const float* up2 = upref + (size_t)user[bg+2]*D_ + d0;
        const float* up3 = upref + (size_t)user[bg+3]*D_ + d0;
        const float* wq = wq_w + (h*2*D_ + d0)*HD_ + e;
        float a0=0, a1=0, a2=0, a3=0;
        #pragma unroll 8
        for (int d = 0; d < 32; d++) {
            float w = wq[d*HD_];
            a0 = fmaf(__ldg(up0 + d), w, a0);
            a1 = fmaf(__ldg(up1 + d), w, a1);
            a2 = fmaf(__ldg(up2 + d), w, a2);
            a3 = fmaf(__ldg(up3 + d), w, a3);
        }
        red[part][e][0] = a0; red[part][e][1] = a1;
        red[part][e][2] = a2; red[part][e][3] = a3;
        __syncthreads();
        if (part < 4) {
            float s = ((red[0][e][part] + red[1][e][part])
                     + (red[2][e][part] + red[3][e][part]))
                    + ((red[4][e][part] + red[5][e][part])
                     + (red[6][e][part] + red[7][e][part]));
            d_qu[(h*B_ + bg + part)*HD_ + e] = s + wq_b[h*HD_ + e];
        }
    }
}

// ---------- Precompute 2: W, st, su, biases.  grid = 144, block = 256 ----------
__global__ __launch_bounds__(256) void kpre2(
        const float* __restrict__ uw, const float* __restrict__ ub,
        const float* __restrict__ hw, const float* __restrict__ hb) {
    int bid = blockIdx.x, tid = threadIdx.x;
    if (bid < 96) {
        int h = bid / 24, t = bid % 24, kt = bid;
        {
            float a0 = 0, a1 = 0, a2 = 0, a3 = 0;
            const float* u = uw + h*HD_*D_ + tid;
            #pragma unroll 4
            for (int e = 0; e < HD_; e += 4) {
                a0 = fmaf(d_v[kt*HD_+e  ], u[(e  )*D_], a0);
                a1 = fmaf(d_v[kt*HD_+e+1], u[(e+1)*D_], a1);
                a2 = fmaf(d_v[kt*HD_+e+2], u[(e+2)*D_], a2);
                a3 = fmaf(d_v[kt*HD_+e+3], u[(e+3)*D_], a3);
            }
            d_W[kt*280 + tid] = (a0 + a1) + (a2 + a3);
        }
        if (tid < 24) {
            float a0 = 0, a1 = 0;
            const float* hwp = hw + h*HD_*T_ + tid;
            #pragma unroll 4
            for (int e = 0; e < HD_; e += 2) {
                a0 = fmaf(d_v[kt*HD_+e  ], hwp[(e  )*T_], a0);
                a1 = fmaf(d_v[kt*HD_+e+1], hwp[(e+1)*T_], a1);
            }
            d_W[kt*280 + 256 + tid] = a0 + a1;
        }
        if (tid >= 32 && tid < 56) {
            int t2 = tid - 32;
            float a0 = 0, a1 = 0;
            #pragma unroll 4
            for (int e = 0; e < HD_; e += 2) {
                a0 = fmaf(d_qt[kt*HD_+e  ], d_k[(h*T_+t2)*HD_+e  ], a0);
                a1 = fmaf(d_qt[kt*HD_+e+1], d_k[(h*T_+t2)*HD_+e+1], a1);
            }
            d_st[(h*T_ + t)*T_ + t2] = (a0 + a1) * 0.125f;
        }
        if (bid == 0) d_bias[tid] = ub[tid];
        if (bid == 1 && tid < 24) d_bias[256 + tid] = hb[tid];
    } else {
        int j = (bid - 96) * 256 + tid;
        int hb2 = j / 24, t = j % 24;
        int h = hb2 >> 7;
        float a0 = 0, a1 = 0, a2 = 0, a3 = 0;
        #pragma unroll 4
        for (int e = 0; e < HD_; e += 4) {
            a0 = fmaf(d_qu[hb2*HD_+e  ], d_k[(h*T_+t)*HD_+e  ], a0);
            a1 = fmaf(d_qu[hb2*HD_+e+1], d_k[(h*T_+t)*HD_+e+1], a1);
            a2 = fmaf(d_qu[hb2*HD_+e+2], d_k[(h*T_+t)*HD_+e+2], a2);
            a3 = fmaf(d_qu[hb2*HD_+e+3], d_k[(h*T_+t)*HD_+e+3], a3);
        }
        d_su[hb2*T_ + t] = ((a0 + a1) + (a2 + a3)) * 0.125f;
    }
}

// ---------- Main fused kernel ----------
#define TR_    128
#define KS_    98                       // ull stride of shPd rows
#define ZS_    98                       // float stride of shZ rows
#define SHPD_B (TR_*KS_*8)              // 100352 bytes
#define QOFF_B 51200                    // queue byte offset (above shZ's 50176)
#define SHWH_O SHPD_B                   // head-W ull[96][12] after shPd
#define SMEM_BYTES (SHPD_B + 96*12*8)   // 109568

__global__ __launch_bounds__(512, 2) void kmain(const int* __restrict__ hour,
                                                const int* __restrict__ mask,
                                                float* __restrict__ out) {
    extern __shared__ char smembuf[];
    ull*   shPd = (ull*)smembuf;                       // probs, duplicated pairs
    float* shZ  = (float*)smembuf;                     // z overlay [128][98]
    ushortx* queue = (ushortx*)(smembuf + QOFF_B);     // <=12288 entries
    ull*   shWh = (ull*)(smembuf + SHWH_O);            // head W pairs [96][12]
    __shared__ int cnt;

    int tid = threadIdx.x;
    int lane = tid & 31;
    int tile0 = blockIdx.x * TR_;
    if (tid == 0) cnt = 0;
    // head-W copy: shWh[kk][c] = (W[kk][256+2c], W[kk][256+2c+1])
    for (int i = tid; i < 96*12; i += 512) {
        int kk = i / 12, c = i - kk*12;
        shWh[i] = *(const ull*)(d_W + kk*280 + 256 + 2*c);
    }
    __syncthreads();

    unsigned ku0 = d_ku[0], ku1 = d_ku[1];
    unsigned kv0 = d_kv[0], kv1 = d_kv[1];

    // ---- Stage A1: z = relu(I); build need-mask; one warp-scan compaction ----
    {
        int r = tid >> 2, h = tid & 3;
        int n = tile0 + r;
        int b = n >> 9;
        int tau = hour[n];
        const int4*   mp  = (const int4*)(mask + n*24);
        const float4* sup = (const float4*)(d_su + (h*B_ + b)*T_);
        const float4* stp = (const float4*)(d_st + (h*T_ + tau)*T_);
        float* zrow = shZ + r*ZS_ + h*24;
        unsigned needmask = 0u;
        #pragma unroll
        for (int j = 0; j < 6; j++) {
            int4 m4 = __ldg(mp + j);
            float4 s4 = sup[j];
            float4 t4 = stp[j];
            int   mv[4] = {m4.x, m4.y, m4.z, m4.w};
            float sv[4] = {s4.x, s4.y, s4.z, s4.w};
            float tv[4] = {t4.x, t4.y, t4.z, t4.w};
            #pragma unroll
            for (int q = 0; q < 4; q++) {
                int t = j*4 + q;
                float z = 0.0f;
                if (!mv[q]) {
                    float I = sv[q] + tv[q];
                    float g = expf((KOSC * I) * I);
                    z = fmaxf(I, 0.0f);
                    if (g != 0.0f) needmask |= (1u << t);
                }
                zrow[t] = z;
            }
        }
        // warp-scan compaction
        int cc = __popc(needmask);
        int pre = cc;
        #pragma unroll
        for (int off = 1; off < 32; off <<= 1) {
            int v = __shfl_up_sync(0xffffffffu, pre, off);
            if (lane >= off) pre += v;
        }
        int wtotal = __shfl_sync(0xffffffffu, pre, 31);
        int base = 0;
        if (lane == 31 && wtotal) base = atomicAdd(&cnt, wtotal);
        base = __shfl_sync(0xffffffffu, base, 31);
        int wpos = base + pre - cc;
        unsigned m = needmask;
        while (m) {
            int t = __ffs(m) - 1;
            m &= m - 1u;
            queue[wpos++] = (ushortx)(tid*24 + t);
        }
    }
    __syncthreads();

    // ---- Stage A2: dense threefry over queued slots ----
    {
        int total = cnt;
        for (int i = tid; i < total; i += 512) {
            int sid = queue[i];
            int t = sid % 24;
            int rh = sid / 24;
            int r = rh >> 2, h = rh & 3;
            int n = tile0 + r;
            int b = n >> 9;
            int tau = hour[n];
            float I = d_su[(h*B_ + b)*T_ + t] + d_st[(h*T_ + tau)*T_ + t];
            float g = expf((KOSC * I) * I);
            unsigned idx = (unsigned)(n*24 + t) + (unsigned)h * (unsigned)NT_;
            unsigned a0, a1, c0, c1;
            tf2x32(ku0, ku1, 0u, idx, a0, a1);
            tf2x32(kv0, kv1, 0u, idx, c0, c1);
            float dn = bits_to_noise(a0 ^ a1) - bits_to_noise(c0 ^ c1);
            shZ[r*ZS_ + h*24 + t] += dn * g;
        }
    }
    __syncthreads();

    // ---- Stage B: softmax in regs; sync; write duplicated pairs ----
    float pp[24];
    {
        int r = tid >> 2, h = tid & 3;
        const float* zrow = shZ + r*ZS_ + h*24;
        #pragma unroll
        for (int t = 0; t < 24; t++) pp[t] = zrow[t];
        float mx = pp[0];
        #pragma unroll
        for (int t = 1; t < 24; t++) mx = fmaxf(mx, pp[t]);
        float s = 0.0f;
        #pragma unroll
        for (int t = 0; t < 24; t++) { pp[t] = expf(pp[t] - mx); s += pp[t]; }
        float inv = 1.0f / s;
        #pragma unroll
        for (int t = 0; t < 24; t++) pp[t] *= inv;
    }
    __syncthreads();   // all z reads done before prob writes overwrite region
    {
        int r = tid >> 2, h = tid & 3;
        float2* dst = (float2*)(shPd + (size_t)r * KS_ + h*24);
        #pragma unroll
        for (int t = 0; t < 24; t++) dst[t] = make_float2(pp[t], pp[t]);
    }
    __syncthreads();

    // ---- Head phase: 24 logit cols; (p,p) pairs x headW col-pairs ----
    {
        int r = tid >> 2, q = tid & 3;
        const ull* prow = shPd + (size_t)r * KS_;
        ull a0 = 0ull, a1 = 0ull, a2 = 0ull;
        #pragma unroll 4
        for (int kk = 0; kk < 96; kk++) {
            ull p2 = prow[kk];
            ffma2(a0, p2, shWh[kk*12 + q*3 + 0]);
            ffma2(a1, p2, shWh[kk*12 + q*3 + 1]);
            ffma2(a2, p2, shWh[kk*12 + q*3 + 2]);
        }
        int n = tile0 + r;
        float* outlg = out + (size_t)N_ * D_ + (size_t)n * T_;
        int cp = q*3;
        float2 f0 = *(float2*)&a0, f1 = *(float2*)&a1, f2 = *(float2*)&a2;
        f0.x += d_bias[256 + 2*cp + 0]; f0.y += d_bias[256 + 2*cp + 1];
        f1.x += d_bias[256 + 2*cp + 2]; f1.y += d_bias[256 + 2*cp + 3];
        f2.x += d_bias[256 + 2*cp + 4]; f2.y += d_bias[256 + 2*cp + 5];
        *(float2*)(outlg + 2*cp + 0) = f0;
        *(float2*)(outlg + 2*cp + 2) = f1;
        *(float2*)(outlg + 2*cp + 4) = f2;
    }

    // ---- Main GEMM: probs[128,96] @ W[96,256], W streamed from L2 ----
    #pragma unroll
    for (int pass = 0; pass < 2; pass++) {
        int u = tid + pass * 512;
        int rg = u >> 6, cs = u & 63;
        int r0 = rg * 8, c0 = cs * 4;
        ull acc0[8], acc1[8];
        #pragma unroll
        for (int i = 0; i < 8; i++) { acc0[i] = 0ull; acc1[i] = 0ull; }
        const float* wbase = d_W + c0;
        #pragma unroll 4
        for (int kk = 0; kk < 96; kk += 2) {
            uint4 wa = __ldg((const uint4*)(wbase + kk*280));
            uint4 wb = __ldg((const uint4*)(wbase + (kk+1)*280));
            ull wax = ((const ulonglong2*)&wa)->x;
            ull way = ((const ulonglong2*)&wa)->y;
            ull wbx = ((const ulonglong2*)&wb)->x;
            ull wby = ((const ulonglong2*)&wb)->y;
            #pragma unroll
            for (int i = 0; i < 8; i++) {
                ulonglong2 pr = *(const ulonglong2*)(shPd + (size_t)(r0+i)*KS_ + kk);
                ffma2(acc0[i], pr.x, wax);
                ffma2(acc1[i], pr.x, way);
                ffma2(acc0[i], pr.y, wbx);
                ffma2(acc1[i], pr.y, wby);
            }
        }
        uint4 bi4 = __ldg((const uint4*)(d_bias + c0));
        ull bix = ((const ulonglong2*)&bi4)->x;
        ull biy = ((const ulonglong2*)&bi4)->y;
        #pragma unroll
        for (int i = 0; i < 8; i++) {
            int n = tile0 + r0 + i;
            ulonglong2 o;
            o.x = addf2(acc0[i], bix);
            o.y = addf2(acc1[i], biy);
            *(ulonglong2*)(out + (size_t)n*D_ + c0) = o;
        }
    }
}

extern "C" void kernel_launch(void* const* d_in, const int* in_sizes, int n_in,
                              void* d_out, int out_size) {
    const float* ts    = (const float*)d_in[0];
    const float* sts   = (const float*)d_in[1];
    const int*   user  = (const int*)d_in[3];
    const int*   hour  = (const int*)d_in[4];
    const int*   mask  = (const int*)d_in[5];
    const float* upref = (const float*)d_in[6];
    const float* wq_w  = (const float*)d_in[7];
    const float* wq_b  = (const float*)d_in[8];
    const float* wk_w  = (const float*)d_in[9];
    const float* wk_b  = (const float*)d_in[10];
    const float* wv_w  = (const float*)d_in[11];
    const float* wv_b  = (const float*)d_in[12];
    const float* uw    = (const float*)d_in[13];
    const float* ub    = (const float*)d_in[14];
    const float* hw    = (const float*)d_in[15];
    const float* hb    = (const float*)d_in[16];
    float* out = (float*)d_out;

    cudaFuncSetAttribute(kmain, cudaFuncAttributeMaxDynamicSharedMemorySize,
                         (int)SMEM_BYTES);

    kpre1<<<224, 512>>>(ts, sts, user, upref, wq_w, wq_b, wk_w, wk_b, wv_w, wv_b);
    kpre2<<<144, 256>>>(uw, ub, hw, hb);
    kmain<<<N_ / TR_, 512, SMEM_BYTES>>>(hour, mask, out);
}

// round 11
// speedup vs baseline: 1.6044x; 1.1393x over previous
#include <cuda_runtime.h>
#include <stdint.h>

#define B_   128
#define S_   512
#define T_   24
#define D_   256
#define H_   4
#define HD_  64
#define N_   (B_*S_)            // 65536
#define NT_  (N_*T_)            // 1572864
#define KOSC (-500.0f)
// noise cutoff: |dn|<=0.165, skip when exp(-500 I^2) < 6e-6  <=>  I^2 > 0.0241
#define NOISE_TH 0.0241f

typedef unsigned long long ull;
typedef unsigned short ushortx;

// Precomputed tables (device globals: no allocation allowed)
__device__ __align__(16) float d_k [H_*T_*HD_];
__device__ __align__(16) float d_v [H_*T_*HD_];
__device__ __align__(16) float d_qt[H_*T_*HD_];
__device__ __align__(16) float d_qu[H_*B_*HD_];
__device__ __align__(16) float d_st[H_*T_*T_];
__device__ __align__(16) float d_su[H_*B_*T_];
__device__ __align__(16) float d_W [96*280];   // [kt][c]: c<256 unify, c>=256 head
__device__ __align__(16) float d_bias[280];
__device__ unsigned d_ku[2];
__device__ unsigned d_kv[2];

// ---------- packed f32x2 helpers ----------
__device__ __forceinline__ void ffma2(ull &d, ull a, ull b) {
    asm("fma.rn.f32x2 %0, %1, %2, %0;" : "+l"(d) : "l"(a), "l"(b));
}
__device__ __forceinline__ ull addf2(ull a, ull b) {
    ull r; asm("add.rn.f32x2 %0, %1, %2;" : "=l"(r) : "l"(a), "l"(b)); return r;
}

// ---------- JAX threefry2x32 (exact) ----------
__device__ __forceinline__ void tf2x32(unsigned k0, unsigned k1,
                                       unsigned x0, unsigned x1,
                                       unsigned &o0, unsigned &o1) {
    unsigned k2 = k0 ^ k1 ^ 0x1BD11BDAu;
    x0 += k0; x1 += k1;
#define RD_(r) { x0 += x1; x1 = (x1 << (r)) | (x1 >> (32 - (r))); x1 ^= x0; }
    RD_(13) RD_(15) RD_(26) RD_(6)   x0 += k1; x1 += k2 + 1u;
    RD_(17) RD_(29) RD_(16) RD_(24)  x0 += k2; x1 += k0 + 2u;
    RD_(13) RD_(15) RD_(26) RD_(6)   x0 += k0; x1 += k1 + 3u;
    RD_(17) RD_(29) RD_(16) RD_(24)  x0 += k1; x1 += k2 + 4u;
    RD_(13) RD_(15) RD_(26) RD_(6)   x0 += k2; x1 += k0 + 5u;
#undef RD_
    o0 = x0; o1 = x1;
}

// XLA ErfInv32 (Giles) with fast log: w = -log(1-x^2), 1-x^2 single-rounded
__device__ __forceinline__ float erfinv_fast(float x) {
    float w = -__logf(fmaf(-x, x, 1.0f));
    float p;
    if (w < 5.0f) {
        w = w - 2.5f;
        p =              2.81022636e-08f;
        p = fmaf(p, w,   3.43273939e-07f);
        p = fmaf(p, w,  -3.5233877e-06f);
        p = fmaf(p, w,  -4.39150654e-06f);
        p = fmaf(p, w,   0.00021858087f);
        p = fmaf(p, w,  -0.00125372503f);
        p = fmaf(p, w,  -0.00417768164f);
        p = fmaf(p, w,   0.246640727f);
        p = fmaf(p, w,   1.50140941f);
    } else {
        w = sqrtf(w) - 3.0f;
        p =             -0.000200214257f;
        p = fmaf(p, w,   0.000100950558f);
        p = fmaf(p, w,   0.00134934322f);
        p = fmaf(p, w,  -0.00367342844f);
        p = fmaf(p, w,   0.00573950773f);
        p = fmaf(p, w,  -0.0076224613f);
        p = fmaf(p, w,   0.00943887047f);
        p = fmaf(p, w,   1.00167406f);
        p = fmaf(p, w,   2.83297682f);
    }
    return p * x;
}

__device__ __forceinline__ float bits_to_noise(unsigned bits) {
    const float LO = -0.99999994039535522461f;
    float u01 = __uint_as_float((bits >> 9) | 0x3f800000u) - 1.0f;
    float val = fmaxf(LO, u01 * 2.0f + LO);
    return 1.41421356237f * erfinv_fast(val) * 0.01f;
}

// ---------- Precompute 1: 96 ktv blocks + 128 qu blocks (4 users each) ----------
__global__ __launch_bounds__(512) void kpre1(
        const float* __restrict__ ts, const float* __restrict__ sts,
        const int* __restrict__ user, const float* __restrict__ upref,
        const float* __restrict__ wq_w, const float* __restrict__ wq_b,
        const float* __restrict__ wk_w, const float* __restrict__ wk_b,
        const float* __restrict__ wv_w, const float* __restrict__ wv_b) {
    __shared__ float redbuf[2048];
    int unit = blockIdx.x;
    int e = threadIdx.x & 63, part = threadIdx.x >> 6;
    int d0 = part * 32;
    if (blockIdx.x == 0 && threadIdx.x == 0) {
        unsigned a0, a1, b0, b1;
        tf2x32(0u, 42u, 0u, 0u, a0, a1);
        tf2x32(0u, 42u, 0u, 1u, b0, b1);
        d_ku[0] = a0; d_ku[1] = a1; d_kv[0] = b0; d_kv[1] = b1;
    }
    if (unit < 96) {
        float (*red)[8][64] = (float(*)[8][64])redbuf;
        int h = unit / 24, t = unit % 24;
        const float* xs = sts + t * D_ + d0;
        const float* xt = ts  + t * D_ + d0;
        const float* wk = wk_w + (h*D_ + d0)*HD_ + e;
        const float* wv = wv_w + (h*D_ + d0)*HD_ + e;
        const float* wq = wq_w + (h*2*D_ + D_ + d0)*HD_ + e;
        float k0=0,k1=0,k2=0,k3=0, v0=0,v1=0,v2=0,v3=0, q0=0,q1=0,q2=0,q3=0;
        #pragma unroll
        for (int d = 0; d < 32; d += 4) {
            float x0 = xs[d], x1 = xs[d+1], x2 = xs[d+2], x3 = xs[d+3];
            k0 = fmaf(x0, wk[(d  )*HD_], k0); k1 = fmaf(x1, wk[(d+1)*HD_], k1);
            k2 = fmaf(x2, wk[(d+2)*HD_], k2); k3 = fmaf(x3, wk[(d+3)*HD_], k3);
            v0 = fmaf(x0, wv[(d  )*HD_], v0); v1 = fmaf(x1, wv[(d+1)*HD_], v1);
            v2 = fmaf(x2, wv[(d+2)*HD_], v2); v3 = fmaf(x3, wv[(d+3)*HD_], v3);
            float y0 = xt[d], y1 = xt[d+1], y2 = xt[d+2], y3 = xt[d+3];
            q0 = fmaf(y0, wq[(d  )*HD_], q0); q1 = fmaf(y1, wq[(d+1)*HD_], q1);
            q2 = fmaf(y2, wq[(d+2)*HD_], q2); q3 = fmaf(y3, wq[(d+3)*HD_], q3);
        }
        red[0][part][e] = (k0 + k1) + (k2 + k3);
        red[1][part][e] = (v0 + v1) + (v2 + v3);
        red[2][part][e] = (q0 + q1) + (q2 + q3);
        __syncthreads();
        if (part < 3) {
            float s = ((red[part][0][e] + red[part][1][e])
                     + (red[part][2][e] + red[part][3][e]))
                    + ((red[part][4][e] + red[part][5][e])
                     + (red[part][6][e] + red[part][7][e]));
            if      (part == 0) d_k [unit*HD_ + e] = s + wk_b[h*HD_ + e];
            else if (part == 1) d_v [unit*HD_ + e] = s + wv_b[h*HD_ + e];
            else                d_qt[unit*HD_ + e] = s;
        }
    } else {
        float (*red)[64][4] = (float(*)[64][4])redbuf;
        int j = unit - 96;                 // 0..127
        int h = j >> 5;                    // 0..3
        int bg = (j & 31) * 4;             // base user row
        const float* up0 = upref + (size_t)user[bg+0]*D_ + d0;
        const float* up1 = upref + (size_t)user[bg+1]*D_ + d0;
        const float* up2 = upref + (size_t)user[bg+2]*D_ + d0;
        const float* up3 = upref + (size_t)user[bg+3]*D_ + d0;
        const float* wq = wq_w + (h*2*D_ + d0)*HD_ + e;
        float a0=0, a1=0, a2=0, a3=0;
        #pragma unroll 8
        for (int d = 0; d < 32; d++) {
            float w = wq[d*HD_];
            a0 = fmaf(__ldg(up0 + d), w, a0);
            a1 = fmaf(__ldg(up1 + d), w, a1);
            a2 = fmaf(__ldg(up2 + d), w, a2);
            a3 = fmaf(__ldg(up3 + d), w, a3);
        }
        red[part][e][0] = a0; red[part][e][1] = a1;
        red[part][e][2] = a2; red[part][e][3] = a3;
        __syncthreads();
        if (part < 4) {
            float s = ((red[0][e][part] + red[1][e][part])
                     + (red[2][e][part] + red[3][e][part]))
                    + ((red[4][e][part] + red[5][e][part])
                     + (red[6][e][part] + red[7][e][part]));
            d_qu[(h*B_ + bg + part)*HD_ + e] = s + wq_b[h*HD_ + e];
        }
    }
}

// ---------- Precompute 2: W, st, su, biases.  grid = 144, block = 256 ----------
__global__ __launch_bounds__(256) void kpre2(
        const float* __restrict__ uw, const float* __restrict__ ub,
        const float* __restrict__ hw, const float* __restrict__ hb) {
    int bid = blockIdx.x, tid = threadIdx.x;
    if (bid < 96) {
        int h = bid / 24, t = bid % 24, kt = bid;
        {
            float a0 = 0, a1 = 0, a2 = 0, a3 = 0;
            const float* u = uw + h*HD_*D_ + tid;
            #pragma unroll 4
            for (int e = 0; e < HD_; e += 4) {
                a0 = fmaf(d_v[kt*HD_+e  ], u[(e  )*D_], a0);
                a1 = fmaf(d_v[kt*HD_+e+1], u[(e+1)*D_], a1);
                a2 = fmaf(d_v[kt*HD_+e+2], u[(e+2)*D_], a2);
                a3 = fmaf(d_v[kt*HD_+e+3], u[(e+3)*D_], a3);
            }
            d_W[kt*280 + tid] = (a0 + a1) + (a2 + a3);
        }
        if (tid < 24) {
            float a0 = 0, a1 = 0;
            const float* hwp = hw + h*HD_*T_ + tid;
            #pragma unroll 4
            for (int e = 0; e < HD_; e += 2) {
                a0 = fmaf(d_v[kt*HD_+e  ], hwp[(e  )*T_], a0);
                a1 = fmaf(d_v[kt*HD_+e+1], hwp[(e+1)*T_], a1);
            }
            d_W[kt*280 + 256 + tid] = a0 + a1;
        }
        if (tid >= 32 && tid < 56) {
            int t2 = tid - 32;
            float a0 = 0, a1 = 0;
            #pragma unroll 4
            for (int e = 0; e < HD_; e += 2) {
                a0 = fmaf(d_qt[kt*HD_+e  ], d_k[(h*T_+t2)*HD_+e  ], a0);
                a1 = fmaf(d_qt[kt*HD_+e+1], d_k[(h*T_+t2)*HD_+e+1], a1);
            }
            d_st[(h*T_ + t)*T_ + t2] = (a0 + a1) * 0.125f;
        }
        if (bid == 0) d_bias[tid] = ub[tid];
        if (bid == 1 && tid < 24) d_bias[256 + tid] = hb[tid];
    } else {
        int j = (bid - 96) * 256 + tid;
        int hb2 = j / 24, t = j % 24;
        int h = hb2 >> 7;
        float a0 = 0, a1 = 0, a2 = 0, a3 = 0;
        #pragma unroll 4
        for (int e = 0; e < HD_; e += 4) {
            a0 = fmaf(d_qu[hb2*HD_+e  ], d_k[(h*T_+t)*HD_+e  ], a0);
            a1 = fmaf(d_qu[hb2*HD_+e+1], d_k[(h*T_+t)*HD_+e+1], a1);
            a2 = fmaf(d_qu[hb2*HD_+e+2], d_k[(h*T_+t)*HD_+e+2], a2);
            a3 = fmaf(d_qu[hb2*HD_+e+3], d_k[(h*T_+t)*HD_+e+3], a3);
        }
        d_su[hb2*T_ + t] = ((a0 + a1) + (a2 + a3)) * 0.125f;
    }
}

// ---------- Main fused kernel ----------
#define TR_    128
#define KS_    98                       // ull stride of shPd rows
#define ZS_    98                       // float stride of shZ rows
#define SHPD_B (TR_*KS_*8)              // 100352 bytes
#define QOFF_B 51200                    // queue byte offset (above shZ's 50176)
#define SHWH_O SHPD_B                   // head-W ull[96][12] after shPd
#define SMEM_BYTES (SHPD_B + 96*12*8)   // 109568

__global__ __launch_bounds__(512, 2) void kmain(const int* __restrict__ hour,
                                                const int* __restrict__ mask,
                                                float* __restrict__ out) {
    extern __shared__ char smembuf[];
    ull*   shPd = (ull*)smembuf;                       // probs, duplicated pairs
    float* shZ  = (float*)smembuf;                     // z overlay [128][98]
    ushortx* queue = (ushortx*)(smembuf + QOFF_B);     // <=12288 entries
    ull*   shWh = (ull*)(smembuf + SHWH_O);            // head W pairs [96][12]
    __shared__ int cnt;

    int tid = threadIdx.x;
    int lane = tid & 31;
    int tile0 = blockIdx.x * TR_;
    if (tid == 0) cnt = 0;
    // head-W copy: shWh[kk][c] = (W[kk][256+2c], W[kk][256+2c+1])
    for (int i = tid; i < 96*12; i += 512) {
        int kk = i / 12, c = i - kk*12;
        shWh[i] = *(const ull*)(d_W + kk*280 + 256 + 2*c);
    }
    __syncthreads();

    unsigned ku0 = d_ku[0], ku1 = d_ku[1];
    unsigned kv0 = d_kv[0], kv1 = d_kv[1];

    // ---- Stage A1: z = relu(I); need test on I^2 (no exp); warp-scan compact ----
    {
        int r = tid >> 2, h = tid & 3;
        int n = tile0 + r;
        int b = n >> 9;
        int tau = hour[n];
        const int4*   mp  = (const int4*)(mask + n*24);
        const float4* sup = (const float4*)(d_su + (h*B_ + b)*T_);
        const float4* stp = (const float4*)(d_st + (h*T_ + tau)*T_);
        float* zrow = shZ + r*ZS_ + h*24;
        unsigned needmask = 0u;
        #pragma unroll
        for (int j = 0; j < 6; j++) {
            int4 m4 = __ldg(mp + j);
            float4 s4 = sup[j];
            float4 t4 = stp[j];
            int   mv[4] = {m4.x, m4.y, m4.z, m4.w};
            float sv[4] = {s4.x, s4.y, s4.z, s4.w};
            float tv[4] = {t4.x, t4.y, t4.z, t4.w};
            #pragma unroll
            for (int q = 0; q < 4; q++) {
                int t = j*4 + q;
                float z = 0.0f;
                if (!mv[q]) {
                    float I = sv[q] + tv[q];
                    z = fmaxf(I, 0.0f);
                    if (I*I < NOISE_TH) needmask |= (1u << t);
                }
                zrow[t] = z;
            }
        }
        // warp-scan compaction
        int cc = __popc(needmask);
        int pre = cc;
        #pragma unroll
        for (int off = 1; off < 32; off <<= 1) {
            int v = __shfl_up_sync(0xffffffffu, pre, off);
            if (lane >= off) pre += v;
        }
        int wtotal = __shfl_sync(0xffffffffu, pre, 31);
        int base = 0;
        if (lane == 31 && wtotal) base = atomicAdd(&cnt, wtotal);
        base = __shfl_sync(0xffffffffu, base, 31);
        int wpos = base + pre - cc;
        unsigned m = needmask;
        while (m) {
            int t = __ffs(m) - 1;
            m &= m - 1u;
            queue[wpos++] = (ushortx)(tid*24 + t);
        }
    }
    __syncthreads();

    // ---- Stage A2: dense threefry over queued slots ----
    {
        int total = cnt;
        for (int i = tid; i < total; i += 512) {
            int sid = queue[i];
            int t = sid % 24;
            int rh = sid / 24;
            int r = rh >> 2, h = rh & 3;
            int n = tile0 + r;
            int b = n >> 9;
            int tau = hour[n];
            float I = d_su[(h*B_ + b)*T_ + t] + d_st[(h*T_ + tau)*T_ + t];
            float g = __expf((KOSC * I) * I);
            unsigned idx = (unsigned)(n*24 + t) + (unsigned)h * (unsigned)NT_;
            unsigned a0, a1, c0, c1;
            tf2x32(ku0, ku1, 0u, idx, a0, a1);
            tf2x32(kv0, kv1, 0u, idx, c0, c1);
            float dn = bits_to_noise(a0 ^ a1) - bits_to_noise(c0 ^ c1);
            shZ[r*ZS_ + h*24 + t] += dn * g;
        }
    }
    __syncthreads();

    // ---- Stage B: softmax in regs; sync; write duplicated pairs ----
    float pp[24];
    {
        int r = tid >> 2, h = tid & 3;
        const float* zrow = shZ + r*ZS_ + h*24;
        #pragma unroll
        for (int t = 0; t < 24; t++) pp[t] = zrow[t];
        float mx = pp[0];
        #pragma unroll
        for (int t = 1; t < 24; t++) mx = fmaxf(mx, pp[t]);
        float s = 0.0f;
        #pragma unroll
        for (int t = 0; t < 24; t++) { pp[t] = __expf(pp[t] - mx); s += pp[t]; }
        float inv = __fdividef(1.0f, s);
        #pragma unroll
        for (int t = 0; t < 24; t++) pp[t] *= inv;
    }
    __syncthreads();   // all z reads done before prob writes overwrite region
    {
        int r = tid >> 2, h = tid & 3;
        float2* dst = (float2*)(shPd + (size_t)r * KS_ + h*24);
        #pragma unroll
        for (int t = 0; t < 24; t++) dst[t] = make_float2(pp[t], pp[t]);
    }
    __syncthreads();

    // ---- Head phase: 24 logit cols; (p,p) pairs x headW col-pairs ----
    {
        int r = tid >> 2, q = tid & 3;
        const ull* prow = shPd + (size_t)r * KS_;
        ull a0 = 0ull, a1 = 0ull, a2 = 0ull;
        #pragma unroll 4
        for (int kk = 0; kk < 96; kk++) {
            ull p2 = prow[kk];
            ffma2(a0, p2, shWh[kk*12 + q*3 + 0]);
            ffma2(a1, p2, shWh[kk*12 + q*3 + 1]);
            ffma2(a2, p2, shWh[kk*12 + q*3 + 2]);
        }
        int n = tile0 + r;
        float* outlg = out + (size_t)N_ * D_ + (size_t)n * T_;
        int cp = q*3;
        float2 f0 = *(float2*)&a0, f1 = *(float2*)&a1, f2 = *(float2*)&a2;
        f0.x += d_bias[256 + 2*cp + 0]; f0.y += d_bias[256 + 2*cp + 1];
        f1.x += d_bias[256 + 2*cp + 2]; f1.y += d_bias[256 + 2*cp + 3];
        f2.x += d_bias[256 + 2*cp + 4]; f2.y += d_bias[256 + 2*cp + 5];
        *(float2*)(outlg + 2*cp + 0) = f0;
        *(float2*)(outlg + 2*cp + 2) = f1;
        *(float2*)(outlg + 2*cp + 4) = f2;
    }

    // ---- Main GEMM: probs[128,96] @ W[96,256], W streamed from L2/L1 ----
    #pragma unroll
    for (int pass = 0; pass < 2; pass++) {
        int u = tid + pass * 512;
        int rg = u >> 6, cs = u & 63;
        int r0 = rg * 8, c0 = cs * 4;
        ull acc0[8], acc1[8];
        #pragma unroll
        for (int i = 0; i < 8; i++) { acc0[i] = 0ull; acc1[i] = 0ull; }
        const float* wbase = d_W + c0;
        #pragma unroll 4
        for (int kk = 0; kk < 96; kk += 2) {
            uint4 wa = __ldg((const uint4*)(wbase + kk*280));
            uint4 wb = __ldg((const uint4*)(wbase + (kk+1)*280));
            ull wax = ((const ulonglong2*)&wa)->x;
            ull way = ((const ulonglong2*)&wa)->y;
            ull wbx = ((const ulonglong2*)&wb)->x;
            ull wby = ((const ulonglong2*)&wb)->y;
            #pragma unroll
            for (int i = 0; i < 8; i++) {
                ulonglong2 pr = *(const ulonglong2*)(shPd + (size_t)(r0+i)*KS_ + kk);
                ffma2(acc0[i], pr.x, wax);
                ffma2(acc1[i], pr.x, way);
                ffma2(acc0[i], pr.y, wbx);
                ffma2(acc1[i], pr.y, wby);
            }
        }
        uint4 bi4 = __ldg((const uint4*)(d_bias + c0));
        ull bix = ((const ulonglong2*)&bi4)->x;
        ull biy = ((const ulonglong2*)&bi4)->y;
        #pragma unroll
        for (int i = 0; i < 8; i++) {
            int n = tile0 + r0 + i;
            ulonglong2 o;
            o.x = addf2(acc0[i], bix);
            o.y = addf2(acc1[i], biy);
            *(ulonglong2*)(out + (size_t)n*D_ + c0) = o;
        }
    }
}

extern "C" void kernel_launch(void* const* d_in, const int* in_sizes, int n_in,
                              void* d_out, int out_size) {
    const float* ts    = (const float*)d_in[0];
    const float* sts   = (const float*)d_in[1];
    const int*   user  = (const int*)d_in[3];
    const int*   hour  = (const int*)d_in[4];
    const int*   mask  = (const int*)d_in[5];
    const float* upref = (const float*)d_in[6];
    const float* wq_w  = (const float*)d_in[7];
    const float* wq_b  = (const float*)d_in[8];
    const float* wk_w  = (const float*)d_in[9];
    const float* wk_b  = (const float*)d_in[10];
    const float* wv_w  = (const float*)d_in[11];
    const float* wv_b  = (const float*)d_in[12];
    const float* uw    = (const float*)d_in[13];
    const float* ub    = (const float*)d_in[14];
    const float* hw    = (const float*)d_in[15];
    const float* hb    = (const float*)d_in[16];
    float* out = (float*)d_out;

    cudaFuncSetAttribute(kmain, cudaFuncAttributeMaxDynamicSharedMemorySize,
                         (int)SMEM_BYTES);

    kpre1<<<224, 512>>>(ts, sts, user, upref, wq_w, wq_b, wk_w, wk_b, wv_w, wv_b);
    kpre2<<<144, 256>>>(uw, ub, hw, hb);
    kmain<<<N_ / TR_, 512, SMEM_BYTES>>>(hour, mask, out);
}